// round 11
// baseline (speedup 1.0000x reference)
#include <cuda_runtime.h>
#include <cuda_bf16.h>
#include <cuda_fp16.h>
#include <math.h>
#include <stdint.h>

// Shapes (fixed by the problem)
#define B_  8
#define C_  64
#define HID_ 256
#define H_  256
#define W_  256
#define HW_ (H_*W_)          // 65536
#define P_  4

#define TILE_PIX 256
#define NTILES   (B_*HW_/TILE_PIX)   // 2048

// Scratch
__device__ float g_y[B_ * C_ * HW_];      // 134 MB
__device__ float g_K[C_ * 16];            // 4 KB

// ---------------------------------------------------------------------------
// Kernel 1: per-channel 4x4 circular-conv kernel from cweight (unchanged).
// ---------------------------------------------------------------------------
__global__ void prep_K_kernel(const float* __restrict__ cw) {
    int c = threadIdx.x;
    if (c >= C_) return;
    float Wr[4][4], Wi[4][4];
#pragma unroll
    for (int u = 0; u < 4; u++) {
#pragma unroll
        for (int v = 0; v < 3; v++) {
            int o = ((u * 3 + v) * C_ + c) * 2;
            Wr[u][v] = cw[o];
            Wi[u][v] = cw[o + 1];
        }
        int mu = (4 - u) & 3;
        int o = ((mu * 3 + 1) * C_ + c) * 2;
        Wr[u][3] = cw[o];
        Wi[u][3] = -cw[o + 1];
    }
    const float ct[4] = {1.f, 0.f, -1.f, 0.f};
    const float st[4] = {0.f, 1.f, 0.f, -1.f};
#pragma unroll
    for (int dp = 0; dp < 4; dp++)
#pragma unroll
        for (int dq = 0; dq < 4; dq++) {
            float s = 0.f;
#pragma unroll
            for (int u = 0; u < 4; u++)
#pragma unroll
                for (int v = 0; v < 4; v++) {
                    int m = (u * dp + v * dq) & 3;
                    s += Wr[u][v] * ct[m] - Wi[u][v] * st[m];
                }
            g_K[c * 16 + dp * 4 + dq] = s * (1.f / 16.f);
        }
}

// ---------------------------------------------------------------------------
// Warp-MMA helpers (sm_80-class PTX: valid on plain sm_103 target)
// ---------------------------------------------------------------------------
__device__ __forceinline__ uint32_t smem_u32(const void* p) {
    uint32_t a;
    asm("{ .reg .u64 t; cvta.to.shared.u64 t, %1; cvt.u32.u64 %0, t; }" : "=r"(a) : "l"(p));
    return a;
}
__device__ __forceinline__ void ldmx4(uint32_t* r, uint32_t addr) {
    asm volatile("ldmatrix.sync.aligned.m8n8.x4.shared.b16 {%0,%1,%2,%3}, [%4];"
        : "=r"(r[0]), "=r"(r[1]), "=r"(r[2]), "=r"(r[3]) : "r"(addr));
}
__device__ __forceinline__ void mma_f16(float* d, const uint32_t* a, const uint32_t* b) {
    asm volatile("mma.sync.aligned.m16n8k16.row.col.f32.f16.f16.f32 "
        "{%0,%1,%2,%3}, {%4,%5,%6,%7}, {%8,%9}, {%0,%1,%2,%3};"
        : "+f"(d[0]), "+f"(d[1]), "+f"(d[2]), "+f"(d[3])
        : "r"(a[0]), "r"(a[1]), "r"(a[2]), "r"(a[3]), "r"(b[0]), "r"(b[1]));
}

// XOR-swizzled byte offset inside a row-major smem tile (16B chunk permute).
__device__ __forceinline__ uint32_t swoff(uint32_t region, int row, int byte_col, int stride) {
    uint32_t b = (uint32_t)byte_col;
    return region + (uint32_t)(row * stride) + (b & 15u) + ((((b >> 4) ^ (uint32_t)(row & 7))) << 4);
}

__device__ __forceinline__ float gelu_exact(float h) {
    return 0.5f * h * (1.0f + erff(h * 0.70710678118654752f));
}
__device__ __forceinline__ uint32_t pack_h2(uint16_t e0, uint16_t e1) {
    return (uint32_t)e0 | ((uint32_t)e1 << 16);
}

// smem regions (bytes). Row-major fp16 tiles with XOR swizzle.
#define R_X     0u         // X  [256p][64k]   stride 128B, 32 KB
#define R_W1    32768u     // W1 [256j][64k]   stride 128B, 32 KB
#define R_W2    65536u     // W2 [64c][256j]   stride 512B, 32 KB
#define R_H     98304u     // H  [256p][256j]  stride 512B, 128 KB
#define R_B1    229376u    // 256 floats
#define R_B2    230400u    // 64 floats
#define SMEM_FFN 230656u   // <= 227 KB opt-in (232448)

// ---------------------------------------------------------------------------
// Kernel 2: FFN via plain fp16 mma.sync (fp32 accum). grid=148, 512 thr.
// Tile = 256 pixels. Full H tile in smem (no half-split):
//   GEMM1: D1[p,j] = X[p,k] W1[j,k]^T, K=64  (warp: 32p x 64j, 2 subtiles)
//   GEMM2: D2[p,c] = H[p,j] W2[c,j]^T, K=256 (warp: 32p x 32c)
// 16 warps -> 4 warps/SMSP for HMMA latency hiding.
// ---------------------------------------------------------------------------
__global__ void __launch_bounds__(512, 1)
ffn_mma_kernel(const float* __restrict__ x,
               const float* __restrict__ w1,
               const float* __restrict__ b1,
               const float* __restrict__ w2,
               const float* __restrict__ b2) {
    extern __shared__ char smc[];
    const uint32_t sb = smem_u32(smc);
    const int tid = threadIdx.x;
    const int lane = tid & 31;
    const int wid = tid >> 5;          // 0..15
    const int wm = (wid & 7) * 32;     // pixel-row group (8 x 32p = 256p)
    const int wn = wid >> 3;           // 0/1: column group

    // ---- one-time: weights -> fp16, swizzled smem ----
    {   // W1: 256 rows x 64 k; thread = (row, half-row)
        const int j = tid >> 1, hf = tid & 1;
        const float* wr = w1 + j * 64 + hf * 32;
#pragma unroll
        for (int g = 0; g < 4; g++) {
            uint16_t hv[8];
#pragma unroll
            for (int e = 0; e < 8; e++) hv[e] = __half_as_ushort(__float2half_rn(wr[g * 8 + e]));
            *reinterpret_cast<uint4*>(smc + swoff(R_W1, j, hf * 64 + g * 16, 128)) = *reinterpret_cast<uint4*>(hv);
        }
    }
    {   // W2: 64 rows x 256 j; thread = (c row, j eighth)
        const int c = tid >> 3, jg = tid & 7;
        const float* wr = w2 + c * 256 + jg * 32;
#pragma unroll
        for (int g = 0; g < 4; g++) {
            uint16_t hv[8];
#pragma unroll
            for (int e = 0; e < 8; e++) hv[e] = __half_as_ushort(__float2half_rn(wr[g * 8 + e]));
            *reinterpret_cast<uint4*>(smc + swoff(R_W2, c, jg * 64 + g * 16, 512)) = *reinterpret_cast<uint4*>(hv);
        }
    }
    if (tid < 256) *reinterpret_cast<float*>(smc + R_B1 + tid * 4) = b1[tid];
    if (tid < 64)  *reinterpret_cast<float*>(smc + R_B2 + tid * 4) = b2[tid];

    const float* b1s = reinterpret_cast<const float*>(smc + R_B1);
    const float* b2s = reinterpret_cast<const float*>(smc + R_B2);

    // ldmatrix per-lane address components (constant per thread)
    const int a_r = lane & 15;
    const int a_b = (lane >> 4) << 4;
    const int b_r = (lane & 7) + ((lane >> 4) << 3);
    const int b_b = ((lane >> 3) & 1) << 4;
    const int prow = lane >> 2;
    const int jcol = (lane & 3) * 2;

    for (int tile = blockIdx.x; tile < NTILES; tile += gridDim.x) {
        const int b = tile >> 8;               // 256 tiles per batch image
        const int pixbase = (tile & 255) << 8;

        // ---- stage X: float4 loads, fp16 round, swizzled store ----
        {
            const int ch = tid >> 3, q = tid & 7;
            const float* xp = x + ((size_t)b << 22) + ((size_t)ch << 16) + pixbase + q * 32;
#pragma unroll
            for (int i4 = 0; i4 < 8; i4++) {
                float4 v = reinterpret_cast<const float4*>(xp)[i4];
                const int r0 = q * 32 + i4 * 4;
                *reinterpret_cast<uint16_t*>(smc + swoff(R_X, r0,     ch * 2, 128)) = __half_as_ushort(__float2half_rn(v.x));
                *reinterpret_cast<uint16_t*>(smc + swoff(R_X, r0 + 1, ch * 2, 128)) = __half_as_ushort(__float2half_rn(v.y));
                *reinterpret_cast<uint16_t*>(smc + swoff(R_X, r0 + 2, ch * 2, 128)) = __half_as_ushort(__float2half_rn(v.z));
                *reinterpret_cast<uint16_t*>(smc + swoff(R_X, r0 + 3, ch * 2, 128)) = __half_as_ushort(__float2half_rn(v.w));
            }
        }
        __syncthreads();

        // ======== GEMM1: warp covers 32p x 64j, 2 j-subtiles ========
#pragma unroll 1
        for (int s = 0; s < 2; s++) {
            const int jbase = wn * 64 + s * 128;
            float acc1[2][8][4];
#pragma unroll
            for (int mt = 0; mt < 2; mt++)
#pragma unroll
                for (int nt = 0; nt < 8; nt++)
#pragma unroll
                    for (int q = 0; q < 4; q++) acc1[mt][nt][q] = 0.f;

#pragma unroll 1
            for (int kt = 0; kt < 4; kt++) {
                uint32_t a0[4], a1[4];
                ldmx4(a0, sb + swoff(R_X, wm + a_r,      kt * 32 + a_b, 128));
                ldmx4(a1, sb + swoff(R_X, wm + 16 + a_r, kt * 32 + a_b, 128));
#pragma unroll
                for (int g = 0; g < 4; g++) {
                    uint32_t bh[4];
                    ldmx4(bh, sb + swoff(R_W1, jbase + g * 16 + b_r, kt * 32 + b_b, 128));
                    mma_f16(acc1[0][2 * g],     a0, bh);
                    mma_f16(acc1[0][2 * g + 1], a0, bh + 2);
                    mma_f16(acc1[1][2 * g],     a1, bh);
                    mma_f16(acc1[1][2 * g + 1], a1, bh + 2);
                }
            }

            // bias + GELU -> fp16 -> H smem
#pragma unroll
            for (int mt = 0; mt < 2; mt++)
#pragma unroll
                for (int nt = 0; nt < 8; nt++) {
                    const int p = wm + mt * 16 + prow;
                    const int j = jbase + nt * 8 + jcol;
                    const float bj0 = b1s[j];
                    const float bj1 = b1s[j + 1];
                    float v0 = gelu_exact(acc1[mt][nt][0] + bj0);
                    float v1 = gelu_exact(acc1[mt][nt][1] + bj1);
                    float v2 = gelu_exact(acc1[mt][nt][2] + bj0);
                    float v3 = gelu_exact(acc1[mt][nt][3] + bj1);
                    uint16_t h0 = __half_as_ushort(__float2half_rn(v0));
                    uint16_t h1 = __half_as_ushort(__float2half_rn(v1));
                    uint16_t h2 = __half_as_ushort(__float2half_rn(v2));
                    uint16_t h3 = __half_as_ushort(__float2half_rn(v3));
                    *reinterpret_cast<uint32_t*>(smc + swoff(R_H, p,     j * 2, 512)) = pack_h2(h0, h1);
                    *reinterpret_cast<uint32_t*>(smc + swoff(R_H, p + 8, j * 2, 512)) = pack_h2(h2, h3);
                }
        }
        __syncthreads();

        // ======== GEMM2: warp covers 32p x 32c, K=256 ========
        float acc2[2][4][4];
#pragma unroll
        for (int mt = 0; mt < 2; mt++)
#pragma unroll
            for (int nt = 0; nt < 4; nt++)
#pragma unroll
                for (int q = 0; q < 4; q++) acc2[mt][nt][q] = 0.f;

        const int c0 = wn * 32;
#pragma unroll 1
        for (int kt = 0; kt < 16; kt++) {
            uint32_t a0[4], a1[4];
            ldmx4(a0, sb + swoff(R_H, wm + a_r,      kt * 32 + a_b, 512));
            ldmx4(a1, sb + swoff(R_H, wm + 16 + a_r, kt * 32 + a_b, 512));
#pragma unroll
            for (int g = 0; g < 2; g++) {
                uint32_t bh[4];
                ldmx4(bh, sb + swoff(R_W2, c0 + g * 16 + b_r, kt * 32 + b_b, 512));
                mma_f16(acc2[0][2 * g],     a0, bh);
                mma_f16(acc2[0][2 * g + 1], a0, bh + 2);
                mma_f16(acc2[1][2 * g],     a1, bh);
                mma_f16(acc2[1][2 * g + 1], a1, bh + 2);
            }
        }

        // ---- epilogue: +b2, write y ----
        float* yb = g_y + ((size_t)b << 22) + pixbase;
#pragma unroll
        for (int mt = 0; mt < 2; mt++)
#pragma unroll
            for (int nt = 0; nt < 4; nt++) {
                const int p = wm + mt * 16 + prow;
                const int c = c0 + nt * 8 + jcol;
                yb[((size_t)c << 16) + p]           = acc2[mt][nt][0] + b2s[c];
                yb[((size_t)(c + 1) << 16) + p]     = acc2[mt][nt][1] + b2s[c + 1];
                yb[((size_t)c << 16) + p + 8]       = acc2[mt][nt][2] + b2s[c];
                yb[((size_t)(c + 1) << 16) + p + 8] = acc2[mt][nt][3] + b2s[c + 1];
            }
        __syncthreads();   // X/H reusable next tile
    }
}

// ---------------------------------------------------------------------------
// Kernel 3: per-window 4x4 circular convolution (unchanged).
// ---------------------------------------------------------------------------
__global__ void __launch_bounds__(256)
winconv_kernel(float* __restrict__ out) {
    const int idx = blockIdx.x * 256 + threadIdx.x;
    const int wx = idx & 63;
    const int wy = (idx >> 6) & 63;
    const int c  = (idx >> 12) & 63;
    const int b  = idx >> 18;

    __shared__ float Ks[16];
    if (threadIdx.x < 16) Ks[threadIdx.x] = g_K[(c << 4) + threadIdx.x];
    __syncthreads();

    float kr[16];
#pragma unroll
    for (int i = 0; i < 16; i++) kr[i] = Ks[i];

    const int base = (((b << 6) + c) << 16) + (wy << 2) * W_ + (wx << 2);
    const float* yp = g_y + base;

    float4 r0 = *reinterpret_cast<const float4*>(yp);
    float4 r1 = *reinterpret_cast<const float4*>(yp + W_);
    float4 r2 = *reinterpret_cast<const float4*>(yp + 2 * W_);
    float4 r3 = *reinterpret_cast<const float4*>(yp + 3 * W_);
    const float vv[16] = {r0.x, r0.y, r0.z, r0.w,
                          r1.x, r1.y, r1.z, r1.w,
                          r2.x, r2.y, r2.z, r2.w,
                          r3.x, r3.y, r3.z, r3.w};

#pragma unroll
    for (int ro = 0; ro < 4; ro++) {
        float o0 = 0.f, o1 = 0.f, o2 = 0.f, o3 = 0.f;
#pragma unroll
        for (int r = 0; r < 4; r++) {
            const int dp4 = ((ro - r) & 3) * 4;
#pragma unroll
            for (int s = 0; s < 4; s++) {
                const float v = vv[r * 4 + s];
                o0 = fmaf(kr[dp4 + ((0 - s) & 3)], v, o0);
                o1 = fmaf(kr[dp4 + ((1 - s) & 3)], v, o1);
                o2 = fmaf(kr[dp4 + ((2 - s) & 3)], v, o2);
                o3 = fmaf(kr[dp4 + ((3 - s) & 3)], v, o3);
            }
        }
        *reinterpret_cast<float4*>(out + base + ro * W_) = make_float4(o0, o1, o2, o3);
    }
}

// ---------------------------------------------------------------------------
extern "C" void kernel_launch(void* const* d_in, const int* in_sizes, int n_in,
                              void* d_out, int out_size) {
    const float* x  = (const float*)d_in[0];
    const float* w1 = (const float*)d_in[1];
    const float* b1 = (const float*)d_in[2];
    const float* w2 = (const float*)d_in[3];
    const float* b2 = (const float*)d_in[4];
    const float* cw = (const float*)d_in[5];
    float* out = (float*)d_out;

    cudaFuncSetAttribute(ffn_mma_kernel, cudaFuncAttributeMaxDynamicSharedMemorySize, SMEM_FFN);

    prep_K_kernel<<<1, 64>>>(cw);
    ffn_mma_kernel<<<148, 512, SMEM_FFN>>>(x, w1, b1, w2, b2);
    winconv_kernel<<<(B_ * C_ * (H_ / P_) * (W_ / P_)) / 256, 256>>>(out);
}

// round 12
// speedup vs baseline: 1.0371x; 1.0371x over previous
#include <cuda_runtime.h>
#include <cuda_bf16.h>
#include <cuda_fp16.h>
#include <math.h>
#include <stdint.h>

// Shapes (fixed by the problem)
#define B_  8
#define C_  64
#define HID_ 256
#define H_  256
#define W_  256
#define HW_ (H_*W_)          // 65536
#define P_  4

#define TILE_PIX 128
#define NTILES   (B_*HW_/TILE_PIX)   // 4096

// Scratch
__device__ float g_y[B_ * C_ * HW_];      // 134 MB

// ---------------------------------------------------------------------------
// Warp-MMA helpers (sm_80-class PTX: valid on plain sm_103 target)
// ---------------------------------------------------------------------------
__device__ __forceinline__ uint32_t smem_u32(const void* p) {
    uint32_t a;
    asm("{ .reg .u64 t; cvta.to.shared.u64 t, %1; cvt.u32.u64 %0, t; }" : "=r"(a) : "l"(p));
    return a;
}
__device__ __forceinline__ void ldmx4(uint32_t* r, uint32_t addr) {
    asm volatile("ldmatrix.sync.aligned.m8n8.x4.shared.b16 {%0,%1,%2,%3}, [%4];"
        : "=r"(r[0]), "=r"(r[1]), "=r"(r[2]), "=r"(r[3]) : "r"(addr));
}
__device__ __forceinline__ void mma_f16(float* d, const uint32_t* a, const uint32_t* b) {
    asm volatile("mma.sync.aligned.m16n8k16.row.col.f32.f16.f16.f32 "
        "{%0,%1,%2,%3}, {%4,%5,%6,%7}, {%8,%9}, {%0,%1,%2,%3};"
        : "+f"(d[0]), "+f"(d[1]), "+f"(d[2]), "+f"(d[3])
        : "r"(a[0]), "r"(a[1]), "r"(a[2]), "r"(a[3]), "r"(b[0]), "r"(b[1]));
}

// XOR-swizzled byte offset inside a row-major smem tile (16B chunk permute).
__device__ __forceinline__ uint32_t swoff(uint32_t region, int row, int byte_col, int stride) {
    uint32_t b = (uint32_t)byte_col;
    return region + (uint32_t)(row * stride) + (b & 15u) + ((((b >> 4) ^ (uint32_t)(row & 7))) << 4);
}

__device__ __forceinline__ float gelu_exact(float h) {
    return 0.5f * h * (1.0f + erff(h * 0.70710678118654752f));
}
__device__ __forceinline__ uint32_t pack_h2(uint16_t e0, uint16_t e1) {
    return (uint32_t)e0 | ((uint32_t)e1 << 16);
}

// smem regions (bytes). Row-major fp16 tiles with XOR swizzle.
// Total 112 KB -> two CTAs per SM.
#define R_X     0u         // X  [128p][64k]   stride 128B, 16 KB
#define R_W1    16384u     // W1 [256j][64k]   stride 128B, 32 KB
#define R_W2    49152u     // W2 [64c][256j]   stride 512B, 32 KB
#define R_H     81920u     // H  [128p][128j]  stride 256B, 32 KB (per half)
#define SMEM_FFN 114688u   // 112 KB

// ---------------------------------------------------------------------------
// FFN via plain fp16 mma.sync (fp32 accum). grid=296 (2 CTAs/SM), 256 thr.
// GEMM1: D1[p,j] = X[p,k] W1[j,k]^T (K=64), two j-halves of 128
// GEMM2: D2[p,c] = H[p,j] W2[c,j]^T (K=256, accumulated over halves)
// Biases read via __ldg (L1-resident after first tile).
// ---------------------------------------------------------------------------
__global__ void __launch_bounds__(256, 2)
ffn_mma_kernel(const float* __restrict__ x,
               const float* __restrict__ w1,
               const float* __restrict__ b1,
               const float* __restrict__ w2,
               const float* __restrict__ b2) {
    extern __shared__ char smc[];
    const uint32_t sb = smem_u32(smc);
    const int tid = threadIdx.x;
    const int lane = tid & 31;
    const int wid = tid >> 5;
    const int wm = (wid & 3) * 32;
    const int wn = wid >> 2;

    // ---- one-time: weights -> fp16, swizzled smem ----
    {   // W1: 256 rows x 64 k; thread = row j
        const int j = tid;
        const float* wr = w1 + j * 64;
#pragma unroll
        for (int g = 0; g < 8; g++) {
            uint16_t hv[8];
#pragma unroll
            for (int e = 0; e < 8; e++) hv[e] = __half_as_ushort(__float2half_rn(wr[g * 8 + e]));
            *reinterpret_cast<uint4*>(smc + swoff(R_W1, j, g * 16, 128)) = *reinterpret_cast<uint4*>(hv);
        }
    }
    {   // W2: 64 rows x 256 j; thread = (c row, j quarter)
        const int c = tid >> 2, jg = tid & 3;
        const float* wr = w2 + c * 256 + jg * 64;
#pragma unroll
        for (int g = 0; g < 8; g++) {
            uint16_t hv[8];
#pragma unroll
            for (int e = 0; e < 8; e++) hv[e] = __half_as_ushort(__float2half_rn(wr[g * 8 + e]));
            *reinterpret_cast<uint4*>(smc + swoff(R_W2, c, jg * 128 + g * 16, 512)) = *reinterpret_cast<uint4*>(hv);
        }
    }

    // ldmatrix per-lane address components (constant per thread)
    const int a_r = lane & 15;
    const int a_b = (lane >> 4) << 4;
    const int b_r = (lane & 7) + ((lane >> 4) << 3);
    const int b_b = ((lane >> 3) & 1) << 4;
    const int prow = lane >> 2;
    const int jcol = (lane & 3) * 2;

    for (int tile = blockIdx.x; tile < NTILES; tile += gridDim.x) {
        const int b = tile >> 9;
        const int pixbase = (tile & 511) << 7;

        // ---- stage X: float4 loads, fp16 round, swizzled store ----
        {
            const int ch = tid >> 2, q = tid & 3;
            const float* xp = x + ((size_t)b << 22) + ((size_t)ch << 16) + pixbase + q * 32;
#pragma unroll
            for (int i4 = 0; i4 < 8; i4++) {
                float4 v = reinterpret_cast<const float4*>(xp)[i4];
                const int r0 = q * 32 + i4 * 4;
                *reinterpret_cast<uint16_t*>(smc + swoff(R_X, r0,     ch * 2, 128)) = __half_as_ushort(__float2half_rn(v.x));
                *reinterpret_cast<uint16_t*>(smc + swoff(R_X, r0 + 1, ch * 2, 128)) = __half_as_ushort(__float2half_rn(v.y));
                *reinterpret_cast<uint16_t*>(smc + swoff(R_X, r0 + 2, ch * 2, 128)) = __half_as_ushort(__float2half_rn(v.z));
                *reinterpret_cast<uint16_t*>(smc + swoff(R_X, r0 + 3, ch * 2, 128)) = __half_as_ushort(__float2half_rn(v.w));
            }
        }
        __syncthreads();

        float acc2[2][4][4];
#pragma unroll
        for (int mt = 0; mt < 2; mt++)
#pragma unroll
            for (int nt = 0; nt < 4; nt++)
#pragma unroll
                for (int q = 0; q < 4; q++) acc2[mt][nt][q] = 0.f;

#pragma unroll 1
        for (int half = 0; half < 2; half++) {
            // ======== GEMM1: 32p x 64j per warp, K=64 ========
            float acc1[2][8][4];
#pragma unroll
            for (int mt = 0; mt < 2; mt++)
#pragma unroll
                for (int nt = 0; nt < 8; nt++)
#pragma unroll
                    for (int q = 0; q < 4; q++) acc1[mt][nt][q] = 0.f;

#pragma unroll 1
            for (int kt = 0; kt < 4; kt++) {
                uint32_t a0[4], a1[4];
                ldmx4(a0, sb + swoff(R_X, wm + a_r,      kt * 32 + a_b, 128));
                ldmx4(a1, sb + swoff(R_X, wm + 16 + a_r, kt * 32 + a_b, 128));
#pragma unroll
                for (int g = 0; g < 4; g++) {
                    const int n0 = half * 128 + wn * 64 + g * 16;
                    uint32_t bh[4];
                    ldmx4(bh, sb + swoff(R_W1, n0 + b_r, kt * 32 + b_b, 128));
                    mma_f16(acc1[0][2 * g],     a0, bh);
                    mma_f16(acc1[0][2 * g + 1], a0, bh + 2);
                    mma_f16(acc1[1][2 * g],     a1, bh);
                    mma_f16(acc1[1][2 * g + 1], a1, bh + 2);
                }
            }

            // ======== bias + GELU -> fp16 -> H smem ========
#pragma unroll
            for (int mt = 0; mt < 2; mt++)
#pragma unroll
                for (int nt = 0; nt < 8; nt++) {
                    const int p = wm + mt * 16 + prow;
                    const int j = wn * 64 + nt * 8 + jcol;
                    const float bj0 = __ldg(b1 + half * 128 + j);
                    const float bj1 = __ldg(b1 + half * 128 + j + 1);
                    float v0 = gelu_exact(acc1[mt][nt][0] + bj0);
                    float v1 = gelu_exact(acc1[mt][nt][1] + bj1);
                    float v2 = gelu_exact(acc1[mt][nt][2] + bj0);
                    float v3 = gelu_exact(acc1[mt][nt][3] + bj1);
                    uint16_t h0 = __half_as_ushort(__float2half_rn(v0));
                    uint16_t h1 = __half_as_ushort(__float2half_rn(v1));
                    uint16_t h2 = __half_as_ushort(__float2half_rn(v2));
                    uint16_t h3 = __half_as_ushort(__float2half_rn(v3));
                    *reinterpret_cast<uint32_t*>(smc + swoff(R_H, p,     j * 2, 256)) = pack_h2(h0, h1);
                    *reinterpret_cast<uint32_t*>(smc + swoff(R_H, p + 8, j * 2, 256)) = pack_h2(h2, h3);
                }
            __syncthreads();

            // ======== GEMM2: 32p x 32c per warp, K=128 this half ========
#pragma unroll 1
            for (int kt = 0; kt < 8; kt++) {
                uint32_t a0[4], a1[4];
                ldmx4(a0, sb + swoff(R_H, wm + a_r,      kt * 32 + a_b, 256));
                ldmx4(a1, sb + swoff(R_H, wm + 16 + a_r, kt * 32 + a_b, 256));
#pragma unroll
                for (int g = 0; g < 2; g++) {
                    const int n0 = wn * 32 + g * 16;
                    const int kb = half * 256 + kt * 32 + b_b;
                    uint32_t bh[4];
                    ldmx4(bh, sb + swoff(R_W2, n0 + b_r, kb, 512));
                    mma_f16(acc2[0][2 * g],     a0, bh);
                    mma_f16(acc2[0][2 * g + 1], a0, bh + 2);
                    mma_f16(acc2[1][2 * g],     a1, bh);
                    mma_f16(acc2[1][2 * g + 1], a1, bh + 2);
                }
            }
            __syncthreads();   // all warps done reading H before next overwrite
        }

        // ---- epilogue: +b2, write y ----
        float* yb = g_y + ((size_t)b << 22) + pixbase;
#pragma unroll
        for (int mt = 0; mt < 2; mt++)
#pragma unroll
            for (int nt = 0; nt < 4; nt++) {
                const int p = wm + mt * 16 + prow;
                const int c = wn * 32 + nt * 8 + jcol;
                const float bc0 = __ldg(b2 + c);
                const float bc1 = __ldg(b2 + c + 1);
                yb[((size_t)c << 16) + p]           = acc2[mt][nt][0] + bc0;
                yb[((size_t)(c + 1) << 16) + p]     = acc2[mt][nt][1] + bc1;
                yb[((size_t)c << 16) + p + 8]       = acc2[mt][nt][2] + bc0;
                yb[((size_t)(c + 1) << 16) + p + 8] = acc2[mt][nt][3] + bc1;
            }
    }
}

// ---------------------------------------------------------------------------
// Winconv: per-window 4x4 circular convolution. K computed inline per block
// (each block covers exactly one channel c).
// ---------------------------------------------------------------------------
__global__ void __launch_bounds__(256)
winconv_kernel(float* __restrict__ out, const float* __restrict__ cw) {
    const int idx = blockIdx.x * 256 + threadIdx.x;
    const int wx = idx & 63;
    const int wy = (idx >> 6) & 63;
    const int c  = (blockIdx.x >> 4) & 63;   // constant per block
    const int b  = blockIdx.x >> 10;

    __shared__ float Ks[16];
    if (threadIdx.x < 16) {
        const int dp = threadIdx.x >> 2, dq = threadIdx.x & 3;
        const float ct[4] = {1.f, 0.f, -1.f, 0.f};
        const float st[4] = {0.f, 1.f, 0.f, -1.f};
        float s = 0.f;
#pragma unroll
        for (int u = 0; u < 4; u++) {
#pragma unroll
            for (int v = 0; v < 4; v++) {
                float wr, wi;
                if (v < 3) {
                    int o = ((u * 3 + v) * C_ + c) * 2;
                    wr = cw[o]; wi = cw[o + 1];
                } else {
                    int mu = (4 - u) & 3;
                    int o = ((mu * 3 + 1) * C_ + c) * 2;
                    wr = cw[o]; wi = -cw[o + 1];
                }
                int m = (u * dp + v * dq) & 3;
                s += wr * ct[m] - wi * st[m];
            }
        }
        Ks[threadIdx.x] = s * (1.f / 16.f);
    }
    __syncthreads();

    float kr[16];
#pragma unroll
    for (int i = 0; i < 16; i++) kr[i] = Ks[i];

    const int base = (((b << 6) + c) << 16) + (wy << 2) * W_ + (wx << 2);
    const float* yp = g_y + base;

    float4 r0 = *reinterpret_cast<const float4*>(yp);
    float4 r1 = *reinterpret_cast<const float4*>(yp + W_);
    float4 r2 = *reinterpret_cast<const float4*>(yp + 2 * W_);
    float4 r3 = *reinterpret_cast<const float4*>(yp + 3 * W_);
    const float vv[16] = {r0.x, r0.y, r0.z, r0.w,
                          r1.x, r1.y, r1.z, r1.w,
                          r2.x, r2.y, r2.z, r2.w,
                          r3.x, r3.y, r3.z, r3.w};

#pragma unroll
    for (int ro = 0; ro < 4; ro++) {
        float o0 = 0.f, o1 = 0.f, o2 = 0.f, o3 = 0.f;
#pragma unroll
        for (int r = 0; r < 4; r++) {
            const int dp4 = ((ro - r) & 3) * 4;
#pragma unroll
            for (int s = 0; s < 4; s++) {
                const float v = vv[r * 4 + s];
                o0 = fmaf(kr[dp4 + ((0 - s) & 3)], v, o0);
                o1 = fmaf(kr[dp4 + ((1 - s) & 3)], v, o1);
                o2 = fmaf(kr[dp4 + ((2 - s) & 3)], v, o2);
                o3 = fmaf(kr[dp4 + ((3 - s) & 3)], v, o3);
            }
        }
        *reinterpret_cast<float4*>(out + base + ro * W_) = make_float4(o0, o1, o2, o3);
    }
}

// ---------------------------------------------------------------------------
extern "C" void kernel_launch(void* const* d_in, const int* in_sizes, int n_in,
                              void* d_out, int out_size) {
    const float* x  = (const float*)d_in[0];
    const float* w1 = (const float*)d_in[1];
    const float* b1 = (const float*)d_in[2];
    const float* w2 = (const float*)d_in[3];
    const float* b2 = (const float*)d_in[4];
    const float* cw = (const float*)d_in[5];
    float* out = (float*)d_out;

    cudaFuncSetAttribute(ffn_mma_kernel, cudaFuncAttributeMaxDynamicSharedMemorySize, SMEM_FFN);

    ffn_mma_kernel<<<296, 256, SMEM_FFN>>>(x, w1, b1, w2, b2);
    winconv_kernel<<<(B_ * C_ * (H_ / P_) * (W_ / P_)) / 256, 256>>>(out, cw);
}

// round 13
// speedup vs baseline: 1.0532x; 1.0155x over previous
#include <cuda_runtime.h>
#include <cuda_bf16.h>
#include <cuda_fp16.h>
#include <math.h>
#include <stdint.h>

// Shapes (fixed by the problem)
#define B_  8
#define C_  64
#define HID_ 256
#define H_  256
#define W_  256
#define HW_ (H_*W_)          // 65536
#define P_  4

// Tile = 4 rows x 32 cols = 128 pixels = 8 complete 4x4 windows.
// 64 row-groups x 8 col-groups x 8 images = 4096 tiles.
#define NTILES 4096

__device__ float g_K[C_ * 16];            // per-channel circular-conv kernel

// ---------------------------------------------------------------------------
// Kernel 1: per-channel 4x4 circular-conv kernel from cweight (validated).
// ---------------------------------------------------------------------------
__global__ void prep_K_kernel(const float* __restrict__ cw) {
    int c = threadIdx.x;
    if (c >= C_) return;
    float Wr[4][4], Wi[4][4];
#pragma unroll
    for (int u = 0; u < 4; u++) {
#pragma unroll
        for (int v = 0; v < 3; v++) {
            int o = ((u * 3 + v) * C_ + c) * 2;
            Wr[u][v] = cw[o];
            Wi[u][v] = cw[o + 1];
        }
        int mu = (4 - u) & 3;
        int o = ((mu * 3 + 1) * C_ + c) * 2;
        Wr[u][3] = cw[o];
        Wi[u][3] = -cw[o + 1];
    }
    const float ct[4] = {1.f, 0.f, -1.f, 0.f};
    const float st[4] = {0.f, 1.f, 0.f, -1.f};
#pragma unroll
    for (int dp = 0; dp < 4; dp++)
#pragma unroll
        for (int dq = 0; dq < 4; dq++) {
            float s = 0.f;
#pragma unroll
            for (int u = 0; u < 4; u++)
#pragma unroll
                for (int v = 0; v < 4; v++) {
                    int m = (u * dp + v * dq) & 3;
                    s += Wr[u][v] * ct[m] - Wi[u][v] * st[m];
                }
            g_K[c * 16 + dp * 4 + dq] = s * (1.f / 16.f);
        }
}

// ---------------------------------------------------------------------------
// Warp-MMA helpers (sm_80-class PTX: valid on plain sm_103 target)
// ---------------------------------------------------------------------------
__device__ __forceinline__ uint32_t smem_u32(const void* p) {
    uint32_t a;
    asm("{ .reg .u64 t; cvta.to.shared.u64 t, %1; cvt.u32.u64 %0, t; }" : "=r"(a) : "l"(p));
    return a;
}
__device__ __forceinline__ void ldmx4(uint32_t* r, uint32_t addr) {
    asm volatile("ldmatrix.sync.aligned.m8n8.x4.shared.b16 {%0,%1,%2,%3}, [%4];"
        : "=r"(r[0]), "=r"(r[1]), "=r"(r[2]), "=r"(r[3]) : "r"(addr));
}
__device__ __forceinline__ void mma_f16(float* d, const uint32_t* a, const uint32_t* b) {
    asm volatile("mma.sync.aligned.m16n8k16.row.col.f32.f16.f16.f32 "
        "{%0,%1,%2,%3}, {%4,%5,%6,%7}, {%8,%9}, {%0,%1,%2,%3};"
        : "+f"(d[0]), "+f"(d[1]), "+f"(d[2]), "+f"(d[3])
        : "r"(a[0]), "r"(a[1]), "r"(a[2]), "r"(a[3]), "r"(b[0]), "r"(b[1]));
}

// XOR-swizzled byte offset inside a row-major smem tile (16B chunk permute).
__device__ __forceinline__ uint32_t swoff(uint32_t region, int row, int byte_col, int stride) {
    uint32_t b = (uint32_t)byte_col;
    return region + (uint32_t)(row * stride) + (b & 15u) + ((((b >> 4) ^ (uint32_t)(row & 7))) << 4);
}

__device__ __forceinline__ float gelu_exact(float h) {
    return 0.5f * h * (1.0f + erff(h * 0.70710678118654752f));
}
__device__ __forceinline__ uint32_t pack_h2(uint16_t e0, uint16_t e1) {
    return (uint32_t)e0 | ((uint32_t)e1 << 16);
}

// ys (fp32, [64c][128p]) float-index with per-channel 16B swizzle.
__device__ __forceinline__ uint32_t ysidx(int c, int p) {
    return (uint32_t)(c * 128 + (p ^ ((c & 7) << 2)));
}

// smem regions (bytes). Total 112 KB -> two CTAs per SM.
#define R_X     0u         // X  [128p][64k] fp16  stride 128B, 16 KB
#define R_W1    16384u     // W1 [256j][64k] fp16  stride 128B, 32 KB
#define R_W2    49152u     // W2 [64c][256j] fp16  stride 512B, 32 KB
#define R_H     81920u     // H  [128p][128j] fp16 stride 256B, 32 KB (per half)
                           // ...aliased as ys [64c][128p] fp32 after GEMM2
#define SMEM_FFN 114688u   // 112 KB

// ---------------------------------------------------------------------------
// Fused FFN + window conv. grid=296 (2 CTAs/SM), 256 thr.
// Tile = 4 rows x 32 cols of one image (8 aligned 4x4 windows).
//   GEMM1: D1[p,j] = X[p,k] W1[j,k]^T (K=64), two j-halves of 128
//   GEMM2: D2[p,c] = H[p,j] W2[c,j]^T (K=256, accumulated over halves)
//   epilogue: D2+b2 -> ys smem -> per-window circular conv -> out
// ---------------------------------------------------------------------------
__global__ void __launch_bounds__(256, 2)
ffn_mma_kernel(const float* __restrict__ x,
               const float* __restrict__ w1,
               const float* __restrict__ b1,
               const float* __restrict__ w2,
               const float* __restrict__ b2,
               float* __restrict__ out) {
    extern __shared__ char smc[];
    const uint32_t sb = smem_u32(smc);
    const int tid = threadIdx.x;
    const int lane = tid & 31;
    const int wid = tid >> 5;
    const int wm = (wid & 3) * 32;
    const int wn = wid >> 2;

    // ---- one-time: weights -> fp16, swizzled smem ----
    {   // W1: 256 rows x 64 k; thread = row j
        const int j = tid;
        const float* wr = w1 + j * 64;
#pragma unroll
        for (int g = 0; g < 8; g++) {
            uint16_t hv[8];
#pragma unroll
            for (int e = 0; e < 8; e++) hv[e] = __half_as_ushort(__float2half_rn(wr[g * 8 + e]));
            *reinterpret_cast<uint4*>(smc + swoff(R_W1, j, g * 16, 128)) = *reinterpret_cast<uint4*>(hv);
        }
    }
    {   // W2: 64 rows x 256 j; thread = (c row, j quarter)
        const int c = tid >> 2, jg = tid & 3;
        const float* wr = w2 + c * 256 + jg * 64;
#pragma unroll
        for (int g = 0; g < 8; g++) {
            uint16_t hv[8];
#pragma unroll
            for (int e = 0; e < 8; e++) hv[e] = __half_as_ushort(__float2half_rn(wr[g * 8 + e]));
            *reinterpret_cast<uint4*>(smc + swoff(R_W2, c, jg * 128 + g * 16, 512)) = *reinterpret_cast<uint4*>(hv);
        }
    }

    // ldmatrix per-lane address components (constant per thread)
    const int a_r = lane & 15;
    const int a_b = (lane >> 4) << 4;
    const int b_r = (lane & 7) + ((lane >> 4) << 3);
    const int b_b = ((lane >> 3) & 1) << 4;
    const int prow = lane >> 2;
    const int jcol = (lane & 3) * 2;

    for (int tile = blockIdx.x; tile < NTILES; tile += gridDim.x) {
        const int b  = tile >> 9;
        const int rem = tile & 511;
        const int rg = rem >> 3;            // row group (0..63): rows rg*4..+3
        const int cg = rem & 7;             // col group (0..7):  cols cg*32..+31
        const int pixoff = rg * 1024 + cg * 32;   // offset within a channel plane

        // ---- stage X: 4 rows x 32 cols per channel; fp16 round; swizzled ----
        {
            const int ch = tid >> 2, q = tid & 3;      // q = local row
            const float* xp = x + ((size_t)b << 22) + ((size_t)ch << 16) + pixoff + q * 256;
#pragma unroll
            for (int i4 = 0; i4 < 8; i4++) {
                float4 v = reinterpret_cast<const float4*>(xp)[i4];
                const int r0 = q * 32 + i4 * 4;        // local pixel p = q*32 + lc
                *reinterpret_cast<uint16_t*>(smc + swoff(R_X, r0,     ch * 2, 128)) = __half_as_ushort(__float2half_rn(v.x));
                *reinterpret_cast<uint16_t*>(smc + swoff(R_X, r0 + 1, ch * 2, 128)) = __half_as_ushort(__float2half_rn(v.y));
                *reinterpret_cast<uint16_t*>(smc + swoff(R_X, r0 + 2, ch * 2, 128)) = __half_as_ushort(__float2half_rn(v.z));
                *reinterpret_cast<uint16_t*>(smc + swoff(R_X, r0 + 3, ch * 2, 128)) = __half_as_ushort(__float2half_rn(v.w));
            }
        }
        __syncthreads();   // also orders prev-tile winconv reads before H writes below

        float acc2[2][4][4];
#pragma unroll
        for (int mt = 0; mt < 2; mt++)
#pragma unroll
            for (int nt = 0; nt < 4; nt++)
#pragma unroll
                for (int q = 0; q < 4; q++) acc2[mt][nt][q] = 0.f;

#pragma unroll 1
        for (int half = 0; half < 2; half++) {
            // ======== GEMM1: 32p x 64j per warp, K=64 ========
            float acc1[2][8][4];
#pragma unroll
            for (int mt = 0; mt < 2; mt++)
#pragma unroll
                for (int nt = 0; nt < 8; nt++)
#pragma unroll
                    for (int q = 0; q < 4; q++) acc1[mt][nt][q] = 0.f;

#pragma unroll 1
            for (int kt = 0; kt < 4; kt++) {
                uint32_t a0[4], a1[4];
                ldmx4(a0, sb + swoff(R_X, wm + a_r,      kt * 32 + a_b, 128));
                ldmx4(a1, sb + swoff(R_X, wm + 16 + a_r, kt * 32 + a_b, 128));
#pragma unroll
                for (int g = 0; g < 4; g++) {
                    const int n0 = half * 128 + wn * 64 + g * 16;
                    uint32_t bh[4];
                    ldmx4(bh, sb + swoff(R_W1, n0 + b_r, kt * 32 + b_b, 128));
                    mma_f16(acc1[0][2 * g],     a0, bh);
                    mma_f16(acc1[0][2 * g + 1], a0, bh + 2);
                    mma_f16(acc1[1][2 * g],     a1, bh);
                    mma_f16(acc1[1][2 * g + 1], a1, bh + 2);
                }
            }

            // ======== bias + GELU -> fp16 -> H smem ========
#pragma unroll
            for (int mt = 0; mt < 2; mt++)
#pragma unroll
                for (int nt = 0; nt < 8; nt++) {
                    const int p = wm + mt * 16 + prow;
                    const int j = wn * 64 + nt * 8 + jcol;
                    const float bj0 = __ldg(b1 + half * 128 + j);
                    const float bj1 = __ldg(b1 + half * 128 + j + 1);
                    float v0 = gelu_exact(acc1[mt][nt][0] + bj0);
                    float v1 = gelu_exact(acc1[mt][nt][1] + bj1);
                    float v2 = gelu_exact(acc1[mt][nt][2] + bj0);
                    float v3 = gelu_exact(acc1[mt][nt][3] + bj1);
                    uint16_t h0 = __half_as_ushort(__float2half_rn(v0));
                    uint16_t h1 = __half_as_ushort(__float2half_rn(v1));
                    uint16_t h2 = __half_as_ushort(__float2half_rn(v2));
                    uint16_t h3 = __half_as_ushort(__float2half_rn(v3));
                    *reinterpret_cast<uint32_t*>(smc + swoff(R_H, p,     j * 2, 256)) = pack_h2(h0, h1);
                    *reinterpret_cast<uint32_t*>(smc + swoff(R_H, p + 8, j * 2, 256)) = pack_h2(h2, h3);
                }
            __syncthreads();

            // ======== GEMM2: 32p x 32c per warp, K=128 this half ========
#pragma unroll 2
            for (int kt = 0; kt < 8; kt++) {
                uint32_t a0[4], a1[4];
                ldmx4(a0, sb + swoff(R_H, wm + a_r,      kt * 32 + a_b, 256));
                ldmx4(a1, sb + swoff(R_H, wm + 16 + a_r, kt * 32 + a_b, 256));
#pragma unroll
                for (int g = 0; g < 2; g++) {
                    const int n0 = wn * 32 + g * 16;
                    const int kb = half * 256 + kt * 32 + b_b;
                    uint32_t bh[4];
                    ldmx4(bh, sb + swoff(R_W2, n0 + b_r, kb, 512));
                    mma_f16(acc2[0][2 * g],     a0, bh);
                    mma_f16(acc2[0][2 * g + 1], a0, bh + 2);
                    mma_f16(acc2[1][2 * g],     a1, bh);
                    mma_f16(acc2[1][2 * g + 1], a1, bh + 2);
                }
            }
            __syncthreads();   // all warps done reading H (also guards ys alias)
        }

        // ---- stage ys: D2 + b2 -> smem [64c][128p] (aliases H) ----
        float* ys = reinterpret_cast<float*>(smc + R_H);
#pragma unroll
        for (int mt = 0; mt < 2; mt++)
#pragma unroll
            for (int nt = 0; nt < 4; nt++) {
                const int p = wm + mt * 16 + prow;
                const int c = wn * 32 + nt * 8 + jcol;
                const float bc0 = __ldg(b2 + c);
                const float bc1 = __ldg(b2 + c + 1);
                ys[ysidx(c,     p)]     = acc2[mt][nt][0] + bc0;
                ys[ysidx(c + 1, p)]     = acc2[mt][nt][1] + bc1;
                ys[ysidx(c,     p + 8)] = acc2[mt][nt][2] + bc0;
                ys[ysidx(c + 1, p + 8)] = acc2[mt][nt][3] + bc1;
            }
        __syncthreads();

        // ---- window conv: 512 items = 64 channels x 8 windows; 2 per thread ----
#pragma unroll
        for (int k2 = 0; k2 < 2; k2++) {
            const int item = tid + k2 * 256;
            const int c = item >> 3;
            const int w = item & 7;

            float kr[16];
#pragma unroll
            for (int i = 0; i < 16; i++) kr[i] = __ldg(g_K + c * 16 + i);

            float vv[16];
#pragma unroll
            for (int r = 0; r < 4; r++) {
                float4 v4 = *reinterpret_cast<const float4*>(ys + ysidx(c, r * 32 + w * 4));
                vv[r * 4 + 0] = v4.x; vv[r * 4 + 1] = v4.y;
                vv[r * 4 + 2] = v4.z; vv[r * 4 + 3] = v4.w;
            }

            float* ob = out + ((size_t)b << 22) + ((size_t)c << 16) + pixoff + w * 4;
#pragma unroll
            for (int ro = 0; ro < 4; ro++) {
                float o0 = 0.f, o1 = 0.f, o2 = 0.f, o3 = 0.f;
#pragma unroll
                for (int r = 0; r < 4; r++) {
                    const int dp4 = ((ro - r) & 3) * 4;
#pragma unroll
                    for (int s = 0; s < 4; s++) {
                        const float v = vv[r * 4 + s];
                        o0 = fmaf(kr[dp4 + ((0 - s) & 3)], v, o0);
                        o1 = fmaf(kr[dp4 + ((1 - s) & 3)], v, o1);
                        o2 = fmaf(kr[dp4 + ((2 - s) & 3)], v, o2);
                        o3 = fmaf(kr[dp4 + ((3 - s) & 3)], v, o3);
                    }
                }
                *reinterpret_cast<float4*>(ob + ro * 256) = make_float4(o0, o1, o2, o3);
            }
        }
        // next-tile X write is to a non-aliased region; the post-X __syncthreads
        // orders these winconv reads before the next H overwrite.
    }
}

// ---------------------------------------------------------------------------
extern "C" void kernel_launch(void* const* d_in, const int* in_sizes, int n_in,
                              void* d_out, int out_size) {
    const float* x  = (const float*)d_in[0];
    const float* w1 = (const float*)d_in[1];
    const float* b1 = (const float*)d_in[2];
    const float* w2 = (const float*)d_in[3];
    const float* b2 = (const float*)d_in[4];
    const float* cw = (const float*)d_in[5];
    float* out = (float*)d_out;

    cudaFuncSetAttribute(ffn_mma_kernel, cudaFuncAttributeMaxDynamicSharedMemorySize, SMEM_FFN);

    prep_K_kernel<<<1, 64>>>(cw);
    ffn_mma_kernel<<<296, 256, SMEM_FFN>>>(x, w1, b1, w2, b2, out);
}

// round 15
// speedup vs baseline: 1.1707x; 1.1115x over previous
#include <cuda_runtime.h>
#include <cuda_bf16.h>
#include <cuda_fp16.h>
#include <math.h>
#include <stdint.h>

// Shapes (fixed by the problem)
#define B_  8
#define C_  64
#define HID_ 256
#define H_  256
#define W_  256
#define HW_ (H_*W_)          // 65536
#define P_  4

// Tile = 4 rows x 32 cols = 128 pixels = 8 complete 4x4 windows.
#define NTILES 4096

__device__ float g_K[C_ * 16];            // per-channel circular-conv kernel

// ---------------------------------------------------------------------------
// Kernel 1: per-channel 4x4 circular-conv kernel from cweight (validated).
// ---------------------------------------------------------------------------
__global__ void prep_K_kernel(const float* __restrict__ cw) {
    int c = threadIdx.x;
    if (c >= C_) return;
    float Wr[4][4], Wi[4][4];
#pragma unroll
    for (int u = 0; u < 4; u++) {
#pragma unroll
        for (int v = 0; v < 3; v++) {
            int o = ((u * 3 + v) * C_ + c) * 2;
            Wr[u][v] = cw[o];
            Wi[u][v] = cw[o + 1];
        }
        int mu = (4 - u) & 3;
        int o = ((mu * 3 + 1) * C_ + c) * 2;
        Wr[u][3] = cw[o];
        Wi[u][3] = -cw[o + 1];
    }
    const float ct[4] = {1.f, 0.f, -1.f, 0.f};
    const float st[4] = {0.f, 1.f, 0.f, -1.f};
#pragma unroll
    for (int dp = 0; dp < 4; dp++)
#pragma unroll
        for (int dq = 0; dq < 4; dq++) {
            float s = 0.f;
#pragma unroll
            for (int u = 0; u < 4; u++)
#pragma unroll
                for (int v = 0; v < 4; v++) {
                    int m = (u * dp + v * dq) & 3;
                    s += Wr[u][v] * ct[m] - Wi[u][v] * st[m];
                }
            g_K[c * 16 + dp * 4 + dq] = s * (1.f / 16.f);
        }
}

// ---------------------------------------------------------------------------
// Warp-MMA helpers
// ---------------------------------------------------------------------------
__device__ __forceinline__ uint32_t smem_u32(const void* p) {
    uint32_t a;
    asm("{ .reg .u64 t; cvta.to.shared.u64 t, %1; cvt.u32.u64 %0, t; }" : "=r"(a) : "l"(p));
    return a;
}
__device__ __forceinline__ void ldmx4(uint32_t* r, uint32_t addr) {
    asm volatile("ldmatrix.sync.aligned.m8n8.x4.shared.b16 {%0,%1,%2,%3}, [%4];"
        : "=r"(r[0]), "=r"(r[1]), "=r"(r[2]), "=r"(r[3]) : "r"(addr));
}
__device__ __forceinline__ void mma_f16(float* d, const uint32_t* a, const uint32_t* b) {
    asm volatile("mma.sync.aligned.m16n8k16.row.col.f32.f16.f16.f32 "
        "{%0,%1,%2,%3}, {%4,%5,%6,%7}, {%8,%9}, {%0,%1,%2,%3};"
        : "+f"(d[0]), "+f"(d[1]), "+f"(d[2]), "+f"(d[3])
        : "r"(a[0]), "r"(a[1]), "r"(a[2]), "r"(a[3]), "r"(b[0]), "r"(b[1]));
}

// XOR-swizzled byte offset inside a row-major smem tile (16B chunk permute).
__device__ __forceinline__ uint32_t swoff(uint32_t region, int row, int byte_col, int stride) {
    uint32_t b = (uint32_t)byte_col;
    return region + (uint32_t)(row * stride) + (b & 15u) + ((((b >> 4) ^ (uint32_t)(row & 7))) << 4);
}

__device__ __forceinline__ float gelu_exact(float h) {
    return 0.5f * h * (1.0f + erff(h * 0.70710678118654752f));
}
__device__ __forceinline__ uint32_t pack_h2(uint16_t e0, uint16_t e1) {
    return (uint32_t)e0 | ((uint32_t)e1 << 16);
}

// ys (fp32, [64c][128p]) float-index with per-channel 16B swizzle.
__device__ __forceinline__ uint32_t ysidx(int c, int p) {
    return (uint32_t)(c * 128 + (p ^ ((c & 7) << 2)));
}

// smem regions (bytes). Total 112 KB -> two CTAs per SM.
#define R_X     0u         // X  [128p][64k] fp16  stride 128B, 16 KB
#define R_W1    16384u     // W1 [256j][64k] fp16  stride 128B, 32 KB
#define R_W2    49152u     // W2 [64c][256j] fp16  stride 512B, 32 KB
#define R_H     81920u     // H  [128p][128j] fp16 stride 256B, 32 KB (per half)
                           // ...aliased as ys [64c][128p] fp32 after GEMM2
#define SMEM_FFN 114688u   // 112 KB

// ---------------------------------------------------------------------------
// Fused FFN + window conv. grid=296 (2 CTAs/SM), 256 thr.
// GEMM1 j-split into 32-wide chunks (acc1 = 32 regs -> no spills @128 cap);
// all kt loops fully unrolled (address math folds to base+const).
// X-stage: R12's validated per-thread 16-bit swizzled stores.
// ---------------------------------------------------------------------------
__global__ void __launch_bounds__(256, 2)
ffn_mma_kernel(const float* __restrict__ x,
               const float* __restrict__ w1,
               const float* __restrict__ b1,
               const float* __restrict__ w2,
               const float* __restrict__ b2,
               float* __restrict__ out) {
    extern __shared__ char smc[];
    const uint32_t sb = smem_u32(smc);
    const int tid = threadIdx.x;
    const int lane = tid & 31;
    const int wid = tid >> 5;
    const int wm = (wid & 3) * 32;
    const int wn = wid >> 2;

    // ---- one-time: weights -> fp16, swizzled smem ----
    {   // W1: 256 rows x 64 k; thread = row j
        const int j = tid;
        const float* wr = w1 + j * 64;
#pragma unroll
        for (int g = 0; g < 8; g++) {
            uint16_t hv[8];
#pragma unroll
            for (int e = 0; e < 8; e++) hv[e] = __half_as_ushort(__float2half_rn(wr[g * 8 + e]));
            *reinterpret_cast<uint4*>(smc + swoff(R_W1, j, g * 16, 128)) = *reinterpret_cast<uint4*>(hv);
        }
    }
    {   // W2: 64 rows x 256 j; thread = (c row, j quarter)
        const int c = tid >> 2, jg = tid & 3;
        const float* wr = w2 + c * 256 + jg * 64;
#pragma unroll
        for (int g = 0; g < 8; g++) {
            uint16_t hv[8];
#pragma unroll
            for (int e = 0; e < 8; e++) hv[e] = __half_as_ushort(__float2half_rn(wr[g * 8 + e]));
            *reinterpret_cast<uint4*>(smc + swoff(R_W2, c, jg * 128 + g * 16, 512)) = *reinterpret_cast<uint4*>(hv);
        }
    }

    // ldmatrix per-lane address components (constant per thread)
    const int a_r = lane & 15;
    const int a_b = (lane >> 4) << 4;
    const int b_r = (lane & 7) + ((lane >> 4) << 3);
    const int b_b = ((lane >> 3) & 1) << 4;
    const int prow = lane >> 2;
    const int jcol = (lane & 3) * 2;

    for (int tile = blockIdx.x; tile < NTILES; tile += gridDim.x) {
        const int b  = tile >> 9;
        const int rem = tile & 511;
        const int rg = rem >> 3;            // row group (0..63)
        const int cg = rem & 7;             // col group (0..7)
        const int pixoff = rg * 1024 + cg * 32;

        // ---- stage X (R12 validated): 4 rows x 32 cols per channel ----
        {
            const int ch = tid >> 2, q = tid & 3;      // q = local row
            const float* xp = x + ((size_t)b << 22) + ((size_t)ch << 16) + pixoff + q * 256;
#pragma unroll
            for (int i4 = 0; i4 < 8; i4++) {
                float4 v = reinterpret_cast<const float4*>(xp)[i4];
                const int r0 = q * 32 + i4 * 4;        // local pixel p = q*32 + lc
                *reinterpret_cast<uint16_t*>(smc + swoff(R_X, r0,     ch * 2, 128)) = __half_as_ushort(__float2half_rn(v.x));
                *reinterpret_cast<uint16_t*>(smc + swoff(R_X, r0 + 1, ch * 2, 128)) = __half_as_ushort(__float2half_rn(v.y));
                *reinterpret_cast<uint16_t*>(smc + swoff(R_X, r0 + 2, ch * 2, 128)) = __half_as_ushort(__float2half_rn(v.z));
                *reinterpret_cast<uint16_t*>(smc + swoff(R_X, r0 + 3, ch * 2, 128)) = __half_as_ushort(__float2half_rn(v.w));
            }
        }
        __syncthreads();

        float acc2[2][4][4];
#pragma unroll
        for (int mt = 0; mt < 2; mt++)
#pragma unroll
            for (int nt = 0; nt < 4; nt++)
#pragma unroll
                for (int q = 0; q < 4; q++) acc2[mt][nt][q] = 0.f;

#pragma unroll 1
        for (int half = 0; half < 2; half++) {
            // ======== GEMM1: two 32-j chunks per warp, K=64, full unroll ========
#pragma unroll 1
            for (int js = 0; js < 2; js++) {
                float acc1[2][4][4];
#pragma unroll
                for (int mt = 0; mt < 2; mt++)
#pragma unroll
                    for (int nt = 0; nt < 4; nt++)
#pragma unroll
                        for (int q = 0; q < 4; q++) acc1[mt][nt][q] = 0.f;

                const int jbase = half * 128 + wn * 64 + js * 32;
#pragma unroll
                for (int kt = 0; kt < 4; kt++) {
                    uint32_t a0[4], a1[4];
                    ldmx4(a0, sb + swoff(R_X, wm + a_r,      kt * 32 + a_b, 128));
                    ldmx4(a1, sb + swoff(R_X, wm + 16 + a_r, kt * 32 + a_b, 128));
#pragma unroll
                    for (int g = 0; g < 2; g++) {
                        uint32_t bh[4];
                        ldmx4(bh, sb + swoff(R_W1, jbase + g * 16 + b_r, kt * 32 + b_b, 128));
                        mma_f16(acc1[0][2 * g],     a0, bh);
                        mma_f16(acc1[0][2 * g + 1], a0, bh + 2);
                        mma_f16(acc1[1][2 * g],     a1, bh);
                        mma_f16(acc1[1][2 * g + 1], a1, bh + 2);
                    }
                }

                // bias + GELU -> fp16 -> H smem (32 j)
#pragma unroll
                for (int mt = 0; mt < 2; mt++)
#pragma unroll
                    for (int nt = 0; nt < 4; nt++) {
                        const int p = wm + mt * 16 + prow;
                        const int jl = wn * 64 + js * 32 + nt * 8 + jcol;     // j within half
                        const float bj0 = __ldg(b1 + half * 128 + jl);
                        const float bj1 = __ldg(b1 + half * 128 + jl + 1);
                        float v0 = gelu_exact(acc1[mt][nt][0] + bj0);
                        float v1 = gelu_exact(acc1[mt][nt][1] + bj1);
                        float v2 = gelu_exact(acc1[mt][nt][2] + bj0);
                        float v3 = gelu_exact(acc1[mt][nt][3] + bj1);
                        uint16_t h0 = __half_as_ushort(__float2half_rn(v0));
                        uint16_t h1 = __half_as_ushort(__float2half_rn(v1));
                        uint16_t h2 = __half_as_ushort(__float2half_rn(v2));
                        uint16_t h3 = __half_as_ushort(__float2half_rn(v3));
                        *reinterpret_cast<uint32_t*>(smc + swoff(R_H, p,     jl * 2, 256)) = pack_h2(h0, h1);
                        *reinterpret_cast<uint32_t*>(smc + swoff(R_H, p + 8, jl * 2, 256)) = pack_h2(h2, h3);
                    }
            }
            __syncthreads();

            // ======== GEMM2: 32p x 32c per warp, K=128, full unroll ========
#pragma unroll
            for (int kt = 0; kt < 8; kt++) {
                uint32_t a0[4], a1[4];
                ldmx4(a0, sb + swoff(R_H, wm + a_r,      kt * 32 + a_b, 256));
                ldmx4(a1, sb + swoff(R_H, wm + 16 + a_r, kt * 32 + a_b, 256));
#pragma unroll
                for (int g = 0; g < 2; g++) {
                    const int n0 = wn * 32 + g * 16;
                    const int kb = half * 256 + kt * 32 + b_b;
                    uint32_t bh[4];
                    ldmx4(bh, sb + swoff(R_W2, n0 + b_r, kb, 512));
                    mma_f16(acc2[0][2 * g],     a0, bh);
                    mma_f16(acc2[0][2 * g + 1], a0, bh + 2);
                    mma_f16(acc2[1][2 * g],     a1, bh);
                    mma_f16(acc2[1][2 * g + 1], a1, bh + 2);
                }
            }
            __syncthreads();   // all warps done reading H (also guards ys alias)
        }

        // ---- stage ys: D2 + b2 -> smem [64c][128p] (aliases H) ----
        float* ys = reinterpret_cast<float*>(smc + R_H);
#pragma unroll
        for (int mt = 0; mt < 2; mt++)
#pragma unroll
            for (int nt = 0; nt < 4; nt++) {
                const int p = wm + mt * 16 + prow;
                const int c = wn * 32 + nt * 8 + jcol;
                const float bc0 = __ldg(b2 + c);
                const float bc1 = __ldg(b2 + c + 1);
                ys[ysidx(c,     p)]     = acc2[mt][nt][0] + bc0;
                ys[ysidx(c + 1, p)]     = acc2[mt][nt][1] + bc1;
                ys[ysidx(c,     p + 8)] = acc2[mt][nt][2] + bc0;
                ys[ysidx(c + 1, p + 8)] = acc2[mt][nt][3] + bc1;
            }
        __syncthreads();

        // ---- window conv: 512 items = 64 channels x 8 windows; 2 per thread ----
#pragma unroll
        for (int k2 = 0; k2 < 2; k2++) {
            const int item = tid + k2 * 256;
            const int c = item >> 3;
            const int w = item & 7;

            float kr[16];
#pragma unroll
            for (int i = 0; i < 16; i++) kr[i] = __ldg(g_K + c * 16 + i);

            float vv[16];
#pragma unroll
            for (int r = 0; r < 4; r++) {
                float4 v4 = *reinterpret_cast<const float4*>(ys + ysidx(c, r * 32 + w * 4));
                vv[r * 4 + 0] = v4.x; vv[r * 4 + 1] = v4.y;
                vv[r * 4 + 2] = v4.z; vv[r * 4 + 3] = v4.w;
            }

            float* ob = out + ((size_t)b << 22) + ((size_t)c << 16) + pixoff + w * 4;
#pragma unroll
            for (int ro = 0; ro < 4; ro++) {
                float o0 = 0.f, o1 = 0.f, o2 = 0.f, o3 = 0.f;
#pragma unroll
                for (int r = 0; r < 4; r++) {
                    const int dp4 = ((ro - r) & 3) * 4;
#pragma unroll
                    for (int s = 0; s < 4; s++) {
                        const float v = vv[r * 4 + s];
                        o0 = fmaf(kr[dp4 + ((0 - s) & 3)], v, o0);
                        o1 = fmaf(kr[dp4 + ((1 - s) & 3)], v, o1);
                        o2 = fmaf(kr[dp4 + ((2 - s) & 3)], v, o2);
                        o3 = fmaf(kr[dp4 + ((3 - s) & 3)], v, o3);
                    }
                }
                *reinterpret_cast<float4*>(ob + ro * 256) = make_float4(o0, o1, o2, o3);
            }
        }
    }
}

// ---------------------------------------------------------------------------
extern "C" void kernel_launch(void* const* d_in, const int* in_sizes, int n_in,
                              void* d_out, int out_size) {
    const float* x  = (const float*)d_in[0];
    const float* w1 = (const float*)d_in[1];
    const float* b1 = (const float*)d_in[2];
    const float* w2 = (const float*)d_in[3];
    const float* b2 = (const float*)d_in[4];
    const float* cw = (const float*)d_in[5];
    float* out = (float*)d_out;

    cudaFuncSetAttribute(ffn_mma_kernel, cudaFuncAttributeMaxDynamicSharedMemorySize, SMEM_FFN);

    prep_K_kernel<<<1, 64>>>(cw);
    ffn_mma_kernel<<<296, 256, SMEM_FFN>>>(x, w1, b1, w2, b2, out);
}

// round 16
// speedup vs baseline: 1.4479x; 1.2368x over previous
#include <cuda_runtime.h>
#include <cuda_bf16.h>
#include <cuda_fp16.h>
#include <math.h>
#include <stdint.h>

// Shapes (fixed by the problem)
#define B_  8
#define C_  64
#define HID_ 256
#define H_  256
#define W_  256
#define HW_ (H_*W_)          // 65536
#define P_  4

// Tile = 4 rows x 32 cols = 128 pixels = 8 complete 4x4 windows.
#define NTILES 4096

__device__ float g_K[C_ * 16];            // per-channel circular-conv kernel

// ---------------------------------------------------------------------------
// Kernel 1: per-channel 4x4 circular-conv kernel from cweight (validated).
// ---------------------------------------------------------------------------
__global__ void prep_K_kernel(const float* __restrict__ cw) {
    int c = threadIdx.x;
    if (c >= C_) return;
    float Wr[4][4], Wi[4][4];
#pragma unroll
    for (int u = 0; u < 4; u++) {
#pragma unroll
        for (int v = 0; v < 3; v++) {
            int o = ((u * 3 + v) * C_ + c) * 2;
            Wr[u][v] = cw[o];
            Wi[u][v] = cw[o + 1];
        }
        int mu = (4 - u) & 3;
        int o = ((mu * 3 + 1) * C_ + c) * 2;
        Wr[u][3] = cw[o];
        Wi[u][3] = -cw[o + 1];
    }
    const float ct[4] = {1.f, 0.f, -1.f, 0.f};
    const float st[4] = {0.f, 1.f, 0.f, -1.f};
#pragma unroll
    for (int dp = 0; dp < 4; dp++)
#pragma unroll
        for (int dq = 0; dq < 4; dq++) {
            float s = 0.f;
#pragma unroll
            for (int u = 0; u < 4; u++)
#pragma unroll
                for (int v = 0; v < 4; v++) {
                    int m = (u * dp + v * dq) & 3;
                    s += Wr[u][v] * ct[m] - Wi[u][v] * st[m];
                }
            g_K[c * 16 + dp * 4 + dq] = s * (1.f / 16.f);
        }
}

// ---------------------------------------------------------------------------
// Warp-MMA helpers
// ---------------------------------------------------------------------------
__device__ __forceinline__ uint32_t smem_u32(const void* p) {
    uint32_t a;
    asm("{ .reg .u64 t; cvta.to.shared.u64 t, %1; cvt.u32.u64 %0, t; }" : "=r"(a) : "l"(p));
    return a;
}
__device__ __forceinline__ void ldmx4(uint32_t* r, uint32_t addr) {
    asm volatile("ldmatrix.sync.aligned.m8n8.x4.shared.b16 {%0,%1,%2,%3}, [%4];"
        : "=r"(r[0]), "=r"(r[1]), "=r"(r[2]), "=r"(r[3]) : "r"(addr));
}
__device__ __forceinline__ void mma_f16(float* d, const uint32_t* a, const uint32_t* b) {
    asm volatile("mma.sync.aligned.m16n8k16.row.col.f32.f16.f16.f32 "
        "{%0,%1,%2,%3}, {%4,%5,%6,%7}, {%8,%9}, {%0,%1,%2,%3};"
        : "+f"(d[0]), "+f"(d[1]), "+f"(d[2]), "+f"(d[3])
        : "r"(a[0]), "r"(a[1]), "r"(a[2]), "r"(a[3]), "r"(b[0]), "r"(b[1]));
}

// XOR-swizzled byte offset inside a row-major smem tile (16B chunk permute).
__device__ __forceinline__ uint32_t swoff(uint32_t region, int row, int byte_col, int stride) {
    uint32_t b = (uint32_t)byte_col;
    return region + (uint32_t)(row * stride) + (b & 15u) + ((((b >> 4) ^ (uint32_t)(row & 7))) << 4);
}

// Fast GELU: tanh formulation with HW tanh.approx.f32 (sm_75+).
// |gelu_tanh - gelu_exact| <= ~4e-4 abs; hidden under fp16 rounding of H.
__device__ __forceinline__ float gelu_fast(float h) {
    float h2 = h * h;
    float u = fmaf(0.044715f * h, h2, h);      // h + 0.044715 h^3
    float a = 0.7978845608028654f * u;         // sqrt(2/pi) * u
    float t;
    asm("tanh.approx.f32 %0, %1;" : "=f"(t) : "f"(a));
    return 0.5f * h * (1.0f + t);
}
__device__ __forceinline__ uint32_t pack_h2(uint16_t e0, uint16_t e1) {
    return (uint32_t)e0 | ((uint32_t)e1 << 16);
}

// ys (fp32, [64c][128p]) float-index with per-channel 16B swizzle.
__device__ __forceinline__ uint32_t ysidx(int c, int p) {
    return (uint32_t)(c * 128 + (p ^ ((c & 7) << 2)));
}

// smem regions (bytes). Total 112 KB -> two CTAs per SM.
#define R_X     0u         // X  [128p][64k] fp16  stride 128B, 16 KB
#define R_W1    16384u     // W1 [256j][64k] fp16  stride 128B, 32 KB
#define R_W2    49152u     // W2 [64c][256j] fp16  stride 512B, 32 KB
#define R_H     81920u     // H  [128p][128j] fp16 stride 256B, 32 KB (per half)
                           // ...aliased as ys [64c][128p] fp32 after GEMM2
#define SMEM_FFN 114688u   // 112 KB

// ---------------------------------------------------------------------------
// Fused FFN + window conv. grid=296 (2 CTAs/SM), 256 thr.
// Identical to R14 except gelu_fast (HW tanh) replaces erff-exact GELU.
// ---------------------------------------------------------------------------
__global__ void __launch_bounds__(256, 2)
ffn_mma_kernel(const float* __restrict__ x,
               const float* __restrict__ w1,
               const float* __restrict__ b1,
               const float* __restrict__ w2,
               const float* __restrict__ b2,
               float* __restrict__ out) {
    extern __shared__ char smc[];
    const uint32_t sb = smem_u32(smc);
    const int tid = threadIdx.x;
    const int lane = tid & 31;
    const int wid = tid >> 5;
    const int wm = (wid & 3) * 32;
    const int wn = wid >> 2;

    // ---- one-time: weights -> fp16, swizzled smem ----
    {   // W1: 256 rows x 64 k; thread = row j
        const int j = tid;
        const float* wr = w1 + j * 64;
#pragma unroll
        for (int g = 0; g < 8; g++) {
            uint16_t hv[8];
#pragma unroll
            for (int e = 0; e < 8; e++) hv[e] = __half_as_ushort(__float2half_rn(wr[g * 8 + e]));
            *reinterpret_cast<uint4*>(smc + swoff(R_W1, j, g * 16, 128)) = *reinterpret_cast<uint4*>(hv);
        }
    }
    {   // W2: 64 rows x 256 j; thread = (c row, j quarter)
        const int c = tid >> 2, jg = tid & 3;
        const float* wr = w2 + c * 256 + jg * 64;
#pragma unroll
        for (int g = 0; g < 8; g++) {
            uint16_t hv[8];
#pragma unroll
            for (int e = 0; e < 8; e++) hv[e] = __half_as_ushort(__float2half_rn(wr[g * 8 + e]));
            *reinterpret_cast<uint4*>(smc + swoff(R_W2, c, jg * 128 + g * 16, 512)) = *reinterpret_cast<uint4*>(hv);
        }
    }

    // ldmatrix per-lane address components (constant per thread)
    const int a_r = lane & 15;
    const int a_b = (lane >> 4) << 4;
    const int b_r = (lane & 7) + ((lane >> 4) << 3);
    const int b_b = ((lane >> 3) & 1) << 4;
    const int prow = lane >> 2;
    const int jcol = (lane & 3) * 2;

    for (int tile = blockIdx.x; tile < NTILES; tile += gridDim.x) {
        const int b  = tile >> 9;
        const int rem = tile & 511;
        const int rg = rem >> 3;            // row group (0..63)
        const int cg = rem & 7;             // col group (0..7)
        const int pixoff = rg * 1024 + cg * 32;

        // ---- stage X: 4 rows x 32 cols per channel; fp16 round; swizzled ----
        {
            const int ch = tid >> 2, q = tid & 3;      // q = local row
            const float* xp = x + ((size_t)b << 22) + ((size_t)ch << 16) + pixoff + q * 256;
#pragma unroll
            for (int i4 = 0; i4 < 8; i4++) {
                float4 v = reinterpret_cast<const float4*>(xp)[i4];
                const int r0 = q * 32 + i4 * 4;
                *reinterpret_cast<uint16_t*>(smc + swoff(R_X, r0,     ch * 2, 128)) = __half_as_ushort(__float2half_rn(v.x));
                *reinterpret_cast<uint16_t*>(smc + swoff(R_X, r0 + 1, ch * 2, 128)) = __half_as_ushort(__float2half_rn(v.y));
                *reinterpret_cast<uint16_t*>(smc + swoff(R_X, r0 + 2, ch * 2, 128)) = __half_as_ushort(__float2half_rn(v.z));
                *reinterpret_cast<uint16_t*>(smc + swoff(R_X, r0 + 3, ch * 2, 128)) = __half_as_ushort(__float2half_rn(v.w));
            }
        }
        __syncthreads();

        float acc2[2][4][4];
#pragma unroll
        for (int mt = 0; mt < 2; mt++)
#pragma unroll
            for (int nt = 0; nt < 4; nt++)
#pragma unroll
                for (int q = 0; q < 4; q++) acc2[mt][nt][q] = 0.f;

#pragma unroll 1
        for (int half = 0; half < 2; half++) {
            // ======== GEMM1: two 32-j chunks per warp, K=64, full unroll ========
#pragma unroll 1
            for (int js = 0; js < 2; js++) {
                float acc1[2][4][4];
#pragma unroll
                for (int mt = 0; mt < 2; mt++)
#pragma unroll
                    for (int nt = 0; nt < 4; nt++)
#pragma unroll
                        for (int q = 0; q < 4; q++) acc1[mt][nt][q] = 0.f;

                const int jbase = half * 128 + wn * 64 + js * 32;
#pragma unroll
                for (int kt = 0; kt < 4; kt++) {
                    uint32_t a0[4], a1[4];
                    ldmx4(a0, sb + swoff(R_X, wm + a_r,      kt * 32 + a_b, 128));
                    ldmx4(a1, sb + swoff(R_X, wm + 16 + a_r, kt * 32 + a_b, 128));
#pragma unroll
                    for (int g = 0; g < 2; g++) {
                        uint32_t bh[4];
                        ldmx4(bh, sb + swoff(R_W1, jbase + g * 16 + b_r, kt * 32 + b_b, 128));
                        mma_f16(acc1[0][2 * g],     a0, bh);
                        mma_f16(acc1[0][2 * g + 1], a0, bh + 2);
                        mma_f16(acc1[1][2 * g],     a1, bh);
                        mma_f16(acc1[1][2 * g + 1], a1, bh + 2);
                    }
                }

                // bias + GELU -> fp16 -> H smem (32 j)
#pragma unroll
                for (int mt = 0; mt < 2; mt++)
#pragma unroll
                    for (int nt = 0; nt < 4; nt++) {
                        const int p = wm + mt * 16 + prow;
                        const int jl = wn * 64 + js * 32 + nt * 8 + jcol;
                        const float bj0 = __ldg(b1 + half * 128 + jl);
                        const float bj1 = __ldg(b1 + half * 128 + jl + 1);
                        float v0 = gelu_fast(acc1[mt][nt][0] + bj0);
                        float v1 = gelu_fast(acc1[mt][nt][1] + bj1);
                        float v2 = gelu_fast(acc1[mt][nt][2] + bj0);
                        float v3 = gelu_fast(acc1[mt][nt][3] + bj1);
                        uint16_t h0 = __half_as_ushort(__float2half_rn(v0));
                        uint16_t h1 = __half_as_ushort(__float2half_rn(v1));
                        uint16_t h2 = __half_as_ushort(__float2half_rn(v2));
                        uint16_t h3 = __half_as_ushort(__float2half_rn(v3));
                        *reinterpret_cast<uint32_t*>(smc + swoff(R_H, p,     jl * 2, 256)) = pack_h2(h0, h1);
                        *reinterpret_cast<uint32_t*>(smc + swoff(R_H, p + 8, jl * 2, 256)) = pack_h2(h2, h3);
                    }
            }
            __syncthreads();

            // ======== GEMM2: 32p x 32c per warp, K=128, full unroll ========
#pragma unroll
            for (int kt = 0; kt < 8; kt++) {
                uint32_t a0[4], a1[4];
                ldmx4(a0, sb + swoff(R_H, wm + a_r,      kt * 32 + a_b, 256));
                ldmx4(a1, sb + swoff(R_H, wm + 16 + a_r, kt * 32 + a_b, 256));
#pragma unroll
                for (int g = 0; g < 2; g++) {
                    const int n0 = wn * 32 + g * 16;
                    const int kb = half * 256 + kt * 32 + b_b;
                    uint32_t bh[4];
                    ldmx4(bh, sb + swoff(R_W2, n0 + b_r, kb, 512));
                    mma_f16(acc2[0][2 * g],     a0, bh);
                    mma_f16(acc2[0][2 * g + 1], a0, bh + 2);
                    mma_f16(acc2[1][2 * g],     a1, bh);
                    mma_f16(acc2[1][2 * g + 1], a1, bh + 2);
                }
            }
            __syncthreads();   // all warps done reading H (also guards ys alias)
        }

        // ---- stage ys: D2 + b2 -> smem [64c][128p] (aliases H) ----
        float* ys = reinterpret_cast<float*>(smc + R_H);
#pragma unroll
        for (int mt = 0; mt < 2; mt++)
#pragma unroll
            for (int nt = 0; nt < 4; nt++) {
                const int p = wm + mt * 16 + prow;
                const int c = wn * 32 + nt * 8 + jcol;
                const float bc0 = __ldg(b2 + c);
                const float bc1 = __ldg(b2 + c + 1);
                ys[ysidx(c,     p)]     = acc2[mt][nt][0] + bc0;
                ys[ysidx(c + 1, p)]     = acc2[mt][nt][1] + bc1;
                ys[ysidx(c,     p + 8)] = acc2[mt][nt][2] + bc0;
                ys[ysidx(c + 1, p + 8)] = acc2[mt][nt][3] + bc1;
            }
        __syncthreads();

        // ---- window conv: 512 items = 64 channels x 8 windows; 2 per thread ----
#pragma unroll
        for (int k2 = 0; k2 < 2; k2++) {
            const int item = tid + k2 * 256;
            const int c = item >> 3;
            const int w = item & 7;

            float kr[16];
#pragma unroll
            for (int i = 0; i < 16; i++) kr[i] = __ldg(g_K + c * 16 + i);

            float vv[16];
#pragma unroll
            for (int r = 0; r < 4; r++) {
                float4 v4 = *reinterpret_cast<const float4*>(ys + ysidx(c, r * 32 + w * 4));
                vv[r * 4 + 0] = v4.x; vv[r * 4 + 1] = v4.y;
                vv[r * 4 + 2] = v4.z; vv[r * 4 + 3] = v4.w;
            }

            float* ob = out + ((size_t)b << 22) + ((size_t)c << 16) + pixoff + w * 4;
#pragma unroll
            for (int ro = 0; ro < 4; ro++) {
                float o0 = 0.f, o1 = 0.f, o2 = 0.f, o3 = 0.f;
#pragma unroll
                for (int r = 0; r < 4; r++) {
                    const int dp4 = ((ro - r) & 3) * 4;
#pragma unroll
                    for (int s = 0; s < 4; s++) {
                        const float v = vv[r * 4 + s];
                        o0 = fmaf(kr[dp4 + ((0 - s) & 3)], v, o0);
                        o1 = fmaf(kr[dp4 + ((1 - s) & 3)], v, o1);
                        o2 = fmaf(kr[dp4 + ((2 - s) & 3)], v, o2);
                        o3 = fmaf(kr[dp4 + ((3 - s) & 3)], v, o3);
                    }
                }
                *reinterpret_cast<float4*>(ob + ro * 256) = make_float4(o0, o1, o2, o3);
            }
        }
    }
}

// ---------------------------------------------------------------------------
extern "C" void kernel_launch(void* const* d_in, const int* in_sizes, int n_in,
                              void* d_out, int out_size) {
    const float* x  = (const float*)d_in[0];
    const float* w1 = (const float*)d_in[1];
    const float* b1 = (const float*)d_in[2];
    const float* w2 = (const float*)d_in[3];
    const float* b2 = (const float*)d_in[4];
    const float* cw = (const float*)d_in[5];
    float* out = (float*)d_out;

    cudaFuncSetAttribute(ffn_mma_kernel, cudaFuncAttributeMaxDynamicSharedMemorySize, SMEM_FFN);

    prep_K_kernel<<<1, 64>>>(cw);
    ffn_mma_kernel<<<296, 256, SMEM_FFN>>>(x, w1, b1, w2, b2, out);
}

// round 17
// speedup vs baseline: 1.4782x; 1.0209x over previous
#include <cuda_runtime.h>
#include <cuda_bf16.h>
#include <cuda_fp16.h>
#include <math.h>
#include <stdint.h>

// Shapes (fixed by the problem)
#define B_  8
#define C_  64
#define HID_ 256
#define H_  256
#define W_  256
#define HW_ (H_*W_)          // 65536
#define P_  4

// Tile = 4 rows x 32 cols = 128 pixels = 8 complete 4x4 windows.
#define NTILES 4096

__device__ float g_K[C_ * 16];            // per-channel circular-conv kernel

// ---------------------------------------------------------------------------
// Kernel 1: per-channel 4x4 circular-conv kernel from cweight (validated).
// ---------------------------------------------------------------------------
__global__ void prep_K_kernel(const float* __restrict__ cw) {
    int c = threadIdx.x;
    if (c >= C_) return;
    float Wr[4][4], Wi[4][4];
#pragma unroll
    for (int u = 0; u < 4; u++) {
#pragma unroll
        for (int v = 0; v < 3; v++) {
            int o = ((u * 3 + v) * C_ + c) * 2;
            Wr[u][v] = cw[o];
            Wi[u][v] = cw[o + 1];
        }
        int mu = (4 - u) & 3;
        int o = ((mu * 3 + 1) * C_ + c) * 2;
        Wr[u][3] = cw[o];
        Wi[u][3] = -cw[o + 1];
    }
    const float ct[4] = {1.f, 0.f, -1.f, 0.f};
    const float st[4] = {0.f, 1.f, 0.f, -1.f};
#pragma unroll
    for (int dp = 0; dp < 4; dp++)
#pragma unroll
        for (int dq = 0; dq < 4; dq++) {
            float s = 0.f;
#pragma unroll
            for (int u = 0; u < 4; u++)
#pragma unroll
                for (int v = 0; v < 4; v++) {
                    int m = (u * dp + v * dq) & 3;
                    s += Wr[u][v] * ct[m] - Wi[u][v] * st[m];
                }
            g_K[c * 16 + dp * 4 + dq] = s * (1.f / 16.f);
        }
}

// ---------------------------------------------------------------------------
// Warp-MMA helpers
// ---------------------------------------------------------------------------
__device__ __forceinline__ uint32_t smem_u32(const void* p) {
    uint32_t a;
    asm("{ .reg .u64 t; cvta.to.shared.u64 t, %1; cvt.u32.u64 %0, t; }" : "=r"(a) : "l"(p));
    return a;
}
__device__ __forceinline__ void ldmx4(uint32_t* r, uint32_t addr) {
    asm volatile("ldmatrix.sync.aligned.m8n8.x4.shared.b16 {%0,%1,%2,%3}, [%4];"
        : "=r"(r[0]), "=r"(r[1]), "=r"(r[2]), "=r"(r[3]) : "r"(addr));
}
__device__ __forceinline__ void mma_f16(float* d, const uint32_t* a, const uint32_t* b) {
    asm volatile("mma.sync.aligned.m16n8k16.row.col.f32.f16.f16.f32 "
        "{%0,%1,%2,%3}, {%4,%5,%6,%7}, {%8,%9}, {%0,%1,%2,%3};"
        : "+f"(d[0]), "+f"(d[1]), "+f"(d[2]), "+f"(d[3])
        : "r"(a[0]), "r"(a[1]), "r"(a[2]), "r"(a[3]), "r"(b[0]), "r"(b[1]));
}

// XOR-swizzled byte offset inside a row-major smem tile (16B chunk permute).
__device__ __forceinline__ uint32_t swoff(uint32_t region, int row, int byte_col, int stride) {
    uint32_t b = (uint32_t)byte_col;
    return region + (uint32_t)(row * stride) + (b & 15u) + ((((b >> 4) ^ (uint32_t)(row & 7))) << 4);
}

// Fast GELU: tanh formulation with HW tanh.approx.f32.
__device__ __forceinline__ float gelu_fast(float h) {
    float h2 = h * h;
    float u = fmaf(0.044715f * h, h2, h);
    float a = 0.7978845608028654f * u;
    float t;
    asm("tanh.approx.f32 %0, %1;" : "=f"(t) : "f"(a));
    return 0.5f * h * (1.0f + t);
}
__device__ __forceinline__ uint32_t pack_h2(uint16_t e0, uint16_t e1) {
    return (uint32_t)e0 | ((uint32_t)e1 << 16);
}
__device__ __forceinline__ uint16_t f2h(float v) {
    return __half_as_ushort(__float2half_rn(v));
}

// ys (fp32, [64c][128p]) float-index with per-channel 16B swizzle.
__device__ __forceinline__ uint32_t ysidx(int c, int p) {
    return (uint32_t)(c * 128 + (p ^ ((c & 7) << 2)));
}

// smem regions (bytes). Total 112 KB -> two CTAs per SM.
#define R_X     0u         // X  [128p][64k] fp16  stride 128B, 16 KB
#define R_W1    16384u     // W1 [256j][64k] fp16  stride 128B, 32 KB
#define R_W2    49152u     // W2 [64c][256j] fp16  stride 512B, 32 KB
#define R_H     81920u     // H  [128p][128j] fp16 stride 256B, 32 KB (per half)
                           // ...aliased as ys [64c][128p] fp32 after GEMM2
#define SMEM_FFN 114688u   // 112 KB

// ---------------------------------------------------------------------------
// Fused FFN + window conv. grid=296 (2 CTAs/SM), 256 thr.
// R16: A-fragments hoisted (loaded once/tile), X-stage STS.32 channel-pair
// packing, winconv re-paired (2 windows of same channel share kr).
// ---------------------------------------------------------------------------
__global__ void __launch_bounds__(256, 2)
ffn_mma_kernel(const float* __restrict__ x,
               const float* __restrict__ w1,
               const float* __restrict__ b1,
               const float* __restrict__ w2,
               const float* __restrict__ b2,
               float* __restrict__ out) {
    extern __shared__ char smc[];
    const uint32_t sb = smem_u32(smc);
    const int tid = threadIdx.x;
    const int lane = tid & 31;
    const int wid = tid >> 5;
    const int wm = (wid & 3) * 32;
    const int wn = wid >> 2;

    // ---- one-time: weights -> fp16, swizzled smem ----
    {   // W1: 256 rows x 64 k; thread = row j
        const int j = tid;
        const float* wr = w1 + j * 64;
#pragma unroll
        for (int g = 0; g < 8; g++) {
            uint16_t hv[8];
#pragma unroll
            for (int e = 0; e < 8; e++) hv[e] = f2h(wr[g * 8 + e]);
            *reinterpret_cast<uint4*>(smc + swoff(R_W1, j, g * 16, 128)) = *reinterpret_cast<uint4*>(hv);
        }
    }
    {   // W2: 64 rows x 256 j; thread = (c row, j quarter)
        const int c = tid >> 2, jg = tid & 3;
        const float* wr = w2 + c * 256 + jg * 64;
#pragma unroll
        for (int g = 0; g < 8; g++) {
            uint16_t hv[8];
#pragma unroll
            for (int e = 0; e < 8; e++) hv[e] = f2h(wr[g * 8 + e]);
            *reinterpret_cast<uint4*>(smc + swoff(R_W2, c, jg * 128 + g * 16, 512)) = *reinterpret_cast<uint4*>(hv);
        }
    }

    // ldmatrix per-lane address components (constant per thread)
    const int a_r = lane & 15;
    const int a_b = (lane >> 4) << 4;
    const int b_r = (lane & 7) + ((lane >> 4) << 3);
    const int b_b = ((lane >> 3) & 1) << 4;
    const int prow = lane >> 2;
    const int jcol = (lane & 3) * 2;

    for (int tile = blockIdx.x; tile < NTILES; tile += gridDim.x) {
        const int bb = tile >> 9;
        const int rem = tile & 511;
        const int rg = rem >> 3;            // row group (0..63)
        const int cg = rem & 7;             // col group (0..7)
        const int pixoff = rg * 1024 + cg * 32;

        // ---- stage X: channel-pair packed STS.32 (correct scalar copies) ----
        {
            const int cp = tid >> 3;        // channel pair 0..31
            const int q  = tid & 7;         // 16-pixel group: pixels q*16..+15
            const int lrow = q >> 1, lcol = (q & 1) * 16;
            const float* xp0 = x + ((size_t)bb << 22) + ((size_t)(2 * cp) << 16) + pixoff + lrow * 256 + lcol;
            const float* xp1 = xp0 + 65536;
            float va[16], vb[16];
#pragma unroll
            for (int i4 = 0; i4 < 4; i4++) {
                float4 u = reinterpret_cast<const float4*>(xp0)[i4];
                va[i4 * 4 + 0] = u.x; va[i4 * 4 + 1] = u.y;
                va[i4 * 4 + 2] = u.z; va[i4 * 4 + 3] = u.w;
                float4 v = reinterpret_cast<const float4*>(xp1)[i4];
                vb[i4 * 4 + 0] = v.x; vb[i4 * 4 + 1] = v.y;
                vb[i4 * 4 + 2] = v.z; vb[i4 * 4 + 3] = v.w;
            }
            const int p0 = q * 16;
#pragma unroll
            for (int i = 0; i < 16; i++) {
                uint32_t wv = pack_h2(f2h(va[i]), f2h(vb[i]));
                *reinterpret_cast<uint32_t*>(smc + swoff(R_X, p0 + i, cp * 4, 128)) = wv;
            }
        }
        __syncthreads();

        // ---- hoisted GEMM1 A-fragments (same for both js chunks and halves) ----
        uint32_t xa[8][4];
#pragma unroll
        for (int kt = 0; kt < 4; kt++) {
            ldmx4(xa[2 * kt],     sb + swoff(R_X, wm + a_r,      kt * 32 + a_b, 128));
            ldmx4(xa[2 * kt + 1], sb + swoff(R_X, wm + 16 + a_r, kt * 32 + a_b, 128));
        }

        float acc2[2][4][4];
#pragma unroll
        for (int mt = 0; mt < 2; mt++)
#pragma unroll
            for (int nt = 0; nt < 4; nt++)
#pragma unroll
                for (int q = 0; q < 4; q++) acc2[mt][nt][q] = 0.f;

#pragma unroll 1
        for (int half = 0; half < 2; half++) {
            // ======== GEMM1: two 32-j chunks per warp, K=64 ========
#pragma unroll 1
            for (int js = 0; js < 2; js++) {
                float acc1[2][4][4];
#pragma unroll
                for (int mt = 0; mt < 2; mt++)
#pragma unroll
                    for (int nt = 0; nt < 4; nt++)
#pragma unroll
                        for (int q = 0; q < 4; q++) acc1[mt][nt][q] = 0.f;

                const int jbase = half * 128 + wn * 64 + js * 32;
#pragma unroll
                for (int kt = 0; kt < 4; kt++) {
#pragma unroll
                    for (int g = 0; g < 2; g++) {
                        uint32_t bh[4];
                        ldmx4(bh, sb + swoff(R_W1, jbase + g * 16 + b_r, kt * 32 + b_b, 128));
                        mma_f16(acc1[0][2 * g],     xa[2 * kt],     bh);
                        mma_f16(acc1[0][2 * g + 1], xa[2 * kt],     bh + 2);
                        mma_f16(acc1[1][2 * g],     xa[2 * kt + 1], bh);
                        mma_f16(acc1[1][2 * g + 1], xa[2 * kt + 1], bh + 2);
                    }
                }

                // bias + GELU -> fp16 -> H smem (32 j)
#pragma unroll
                for (int mt = 0; mt < 2; mt++)
#pragma unroll
                    for (int nt = 0; nt < 4; nt++) {
                        const int p = wm + mt * 16 + prow;
                        const int jl = wn * 64 + js * 32 + nt * 8 + jcol;
                        const float bj0 = __ldg(b1 + half * 128 + jl);
                        const float bj1 = __ldg(b1 + half * 128 + jl + 1);
                        float v0 = gelu_fast(acc1[mt][nt][0] + bj0);
                        float v1 = gelu_fast(acc1[mt][nt][1] + bj1);
                        float v2 = gelu_fast(acc1[mt][nt][2] + bj0);
                        float v3 = gelu_fast(acc1[mt][nt][3] + bj1);
                        *reinterpret_cast<uint32_t*>(smc + swoff(R_H, p,     jl * 2, 256)) = pack_h2(f2h(v0), f2h(v1));
                        *reinterpret_cast<uint32_t*>(smc + swoff(R_H, p + 8, jl * 2, 256)) = pack_h2(f2h(v2), f2h(v3));
                    }
            }
            __syncthreads();

            // ======== GEMM2: 32p x 32c per warp, K=128, full unroll ========
#pragma unroll
            for (int kt = 0; kt < 8; kt++) {
                uint32_t a0[4], a1[4];
                ldmx4(a0, sb + swoff(R_H, wm + a_r,      kt * 32 + a_b, 256));
                ldmx4(a1, sb + swoff(R_H, wm + 16 + a_r, kt * 32 + a_b, 256));
#pragma unroll
                for (int g = 0; g < 2; g++) {
                    const int n0 = wn * 32 + g * 16;
                    const int kb = half * 256 + kt * 32 + b_b;
                    uint32_t bh[4];
                    ldmx4(bh, sb + swoff(R_W2, n0 + b_r, kb, 512));
                    mma_f16(acc2[0][2 * g],     a0, bh);
                    mma_f16(acc2[0][2 * g + 1], a0, bh + 2);
                    mma_f16(acc2[1][2 * g],     a1, bh);
                    mma_f16(acc2[1][2 * g + 1], a1, bh + 2);
                }
            }
            __syncthreads();   // all warps done reading H (also guards ys alias)
        }

        // ---- stage ys: D2 + b2 -> smem [64c][128p] (aliases H) ----
        float* ys = reinterpret_cast<float*>(smc + R_H);
#pragma unroll
        for (int mt = 0; mt < 2; mt++)
#pragma unroll
            for (int nt = 0; nt < 4; nt++) {
                const int p = wm + mt * 16 + prow;
                const int c = wn * 32 + nt * 8 + jcol;
                const float bc0 = __ldg(b2 + c);
                const float bc1 = __ldg(b2 + c + 1);
                ys[ysidx(c,     p)]     = acc2[mt][nt][0] + bc0;
                ys[ysidx(c + 1, p)]     = acc2[mt][nt][1] + bc1;
                ys[ysidx(c,     p + 8)] = acc2[mt][nt][2] + bc0;
                ys[ysidx(c + 1, p + 8)] = acc2[mt][nt][3] + bc1;
            }
        __syncthreads();

        // ---- window conv: thread = (channel c, 2 windows); kr loaded once ----
        {
            const int c  = tid >> 2;            // 0..63
            const int w0 = (tid & 3) * 2;       // windows w0, w0+1

            float kr[16];
#pragma unroll
            for (int i = 0; i < 16; i++) kr[i] = __ldg(g_K + c * 16 + i);

#pragma unroll
            for (int wq = 0; wq < 2; wq++) {
                const int w = w0 + wq;
                float vv[16];
#pragma unroll
                for (int r = 0; r < 4; r++) {
                    float4 v4 = *reinterpret_cast<const float4*>(ys + ysidx(c, r * 32 + w * 4));
                    vv[r * 4 + 0] = v4.x; vv[r * 4 + 1] = v4.y;
                    vv[r * 4 + 2] = v4.z; vv[r * 4 + 3] = v4.w;
                }

                float* ob = out + ((size_t)bb << 22) + ((size_t)c << 16) + pixoff + w * 4;
#pragma unroll
                for (int ro = 0; ro < 4; ro++) {
                    float o0 = 0.f, o1 = 0.f, o2 = 0.f, o3 = 0.f;
#pragma unroll
                    for (int r = 0; r < 4; r++) {
                        const int dp4 = ((ro - r) & 3) * 4;
#pragma unroll
                        for (int s = 0; s < 4; s++) {
                            const float v = vv[r * 4 + s];
                            o0 = fmaf(kr[dp4 + ((0 - s) & 3)], v, o0);
                            o1 = fmaf(kr[dp4 + ((1 - s) & 3)], v, o1);
                            o2 = fmaf(kr[dp4 + ((2 - s) & 3)], v, o2);
                            o3 = fmaf(kr[dp4 + ((3 - s) & 3)], v, o3);
                        }
                    }
                    *reinterpret_cast<float4*>(ob + ro * 256) = make_float4(o0, o1, o2, o3);
                }
            }
        }
    }
}

// ---------------------------------------------------------------------------
extern "C" void kernel_launch(void* const* d_in, const int* in_sizes, int n_in,
                              void* d_out, int out_size) {
    const float* x  = (const float*)d_in[0];
    const float* w1 = (const float*)d_in[1];
    const float* b1 = (const float*)d_in[2];
    const float* w2 = (const float*)d_in[3];
    const float* b2 = (const float*)d_in[4];
    const float* cw = (const float*)d_in[5];
    float* out = (float*)d_out;

    cudaFuncSetAttribute(ffn_mma_kernel, cudaFuncAttributeMaxDynamicSharedMemorySize, SMEM_FFN);

    prep_K_kernel<<<1, 64>>>(cw);
    ffn_mma_kernel<<<296, 256, SMEM_FFN>>>(x, w1, b1, w2, b2, out);
}